// round 4
// baseline (speedup 1.0000x reference)
#include <cuda_runtime.h>
#include <math.h>

#define S_LEN   2048
#define D_MODEL 1024
#define NH      16
#define HD      64
#define BATCH   4
#define M_TOTAL (BATCH * S_LEN)          // 8192
#define PLANE   (8192 * 1024)            // elems per Q/K/V plane

// Scratch for Q,K,V in [b,h,s,d] layout (3 * 32MB). Allocation-free rule:
// __device__ globals are the sanctioned scratch mechanism.
__device__ float g_qkv[3ull * PLANE];

// ---------------------------------------------------------------------------
// Kernel 1: fused QKV projection.  C = X @ W^T + b
//   X: [8192, 1024] row-major, W: [1024, 1024] row-major (torch Linear weight)
//   Output scattered directly to [b, h, s, d] so attention reads contiguously.
// Tiles: 64x64, K-step 32, 4x4 micro-tile, 256 threads.
// Smem staged transposed [k][m]/[k][n] with +1 pad: conflict-free scatter
// stores (bank = (k+m) mod 32 covers all 32), <=2-way read conflicts.
// ---------------------------------------------------------------------------
#define BM 64
#define BN 64
#define BK 32

__global__ __launch_bounds__(256) void qkv_gemm(
    const float* __restrict__ X,
    const float* __restrict__ Wq, const float* __restrict__ bq,
    const float* __restrict__ Wk, const float* __restrict__ bk,
    const float* __restrict__ Wv, const float* __restrict__ bv)
{
    const int z = blockIdx.z;
    const float* W    = (z == 0) ? Wq : (z == 1) ? Wk : Wv;
    const float* bias = (z == 0) ? bq : (z == 1) ? bk : bv;
    float* Out = g_qkv + (size_t)z * PLANE;

    __shared__ float As[BK][BM + 1];   // [k][m]
    __shared__ float Bs[BK][BN + 1];   // [k][n]

    const int tx = threadIdx.x, ty = threadIdx.y;
    const int tid = ty * 16 + tx;
    const int m0 = blockIdx.y * BM;
    const int n0 = blockIdx.x * BN;

    float acc[4][4];
    #pragma unroll
    for (int i = 0; i < 4; i++)
        #pragma unroll
        for (int j = 0; j < 4; j++) acc[i][j] = 0.f;

    for (int k0 = 0; k0 < D_MODEL; k0 += BK) {
        // Stage A and B tiles (coalesced float4 global loads, transposed smem)
        #pragma unroll
        for (int it = 0; it < 2; it++) {
            int idx = tid + it * 256;   // 0..511
            int r   = idx >> 3;         // row within tile 0..63
            int c4  = idx & 7;          // float4 column 0..7
            float4 a = *(const float4*)(X + (size_t)(m0 + r) * D_MODEL + k0 + c4 * 4);
            As[c4 * 4 + 0][r] = a.x; As[c4 * 4 + 1][r] = a.y;
            As[c4 * 4 + 2][r] = a.z; As[c4 * 4 + 3][r] = a.w;
            float4 b = *(const float4*)(W + (size_t)(n0 + r) * D_MODEL + k0 + c4 * 4);
            Bs[c4 * 4 + 0][r] = b.x; Bs[c4 * 4 + 1][r] = b.y;
            Bs[c4 * 4 + 2][r] = b.z; Bs[c4 * 4 + 3][r] = b.w;
        }
        __syncthreads();

        #pragma unroll
        for (int kk = 0; kk < BK; kk++) {
            float a[4], b[4];
            #pragma unroll
            for (int i = 0; i < 4; i++) a[i] = As[kk][ty * 4 + i];
            #pragma unroll
            for (int j = 0; j < 4; j++) b[j] = Bs[kk][tx * 4 + j];
            #pragma unroll
            for (int i = 0; i < 4; i++)
                #pragma unroll
                for (int j = 0; j < 4; j++)
                    acc[i][j] = fmaf(a[i], b[j], acc[i][j]);
        }
        __syncthreads();
    }

    // Epilogue: bias + scatter into [b, h, s, d]
    #pragma unroll
    for (int i = 0; i < 4; i++) {
        int m  = m0 + ty * 4 + i;
        int b_ = m >> 11;            // / 2048
        int s_ = m & 2047;
        #pragma unroll
        for (int j = 0; j < 4; j++) {
            int n = n0 + tx * 4 + j;
            int h = n >> 6;
            int d = n & 63;
            Out[(((size_t)(b_ * NH + h) * S_LEN + s_) << 6) + d] = acc[i][j] + bias[n];
        }
    }
}

// ---------------------------------------------------------------------------
// Kernel 2: causal flash attention, fp32.
// One block = 64 query rows of one (b,h). Online softmax, 4x4 micro-tiles.
// Row reductions via width-16 shuffles (lanes 0-15 / 16-31 each own one
// ty-group, i.e. the same 4 query rows).
// ---------------------------------------------------------------------------
__global__ __launch_bounds__(256) void attn_kernel(
    const int* __restrict__ amask, float* __restrict__ out)
{
    extern __shared__ float smem[];
    float (*Qs)[65] = (float(*)[65])(smem);                 // [d][q]
    float (*Ks)[65] = (float(*)[65])(smem + 64 * 65);       // [d][k]
    float (*Vs)[65] = (float(*)[65])(smem + 2 * 64 * 65);   // [k][d]
    float (*Ps)[65] = (float(*)[65])(smem + 3 * 64 * 65);   // [k][q]

    const int qt = blockIdx.x;      // query tile 0..31
    const int bh = blockIdx.y;      // 0..63
    const int b_ = bh >> 4;
    const int h  = bh & 15;
    const int q0 = qt * 64;

    const float* Qb = g_qkv + (size_t)bh * S_LEN * HD;
    const float* Kb = g_qkv + (size_t)PLANE + (size_t)bh * S_LEN * HD;
    const float* Vb = g_qkv + 2ull * PLANE + (size_t)bh * S_LEN * HD;

    const int tx = threadIdx.x, ty = threadIdx.y;
    const int tid = ty * 16 + tx;

    // Load Q tile, transposed to [d][q]
    #pragma unroll
    for (int it = 0; it < 4; it++) {
        int idx = tid + it * 256;   // 0..1023
        int r   = idx >> 4;         // q row 0..63
        int c   = idx & 15;         // float4 col 0..15
        float4 a = *(const float4*)(Qb + (size_t)(q0 + r) * HD + c * 4);
        Qs[c * 4 + 0][r] = a.x; Qs[c * 4 + 1][r] = a.y;
        Qs[c * 4 + 2][r] = a.z; Qs[c * 4 + 3][r] = a.w;
    }

    float m_run[4], l_run[4], acc[4][4];
    #pragma unroll
    for (int i = 0; i < 4; i++) {
        m_run[i] = -1e30f; l_run[i] = 0.f;
        #pragma unroll
        for (int j = 0; j < 4; j++) acc[i][j] = 0.f;
    }

    for (int j0 = 0; j0 <= q0; j0 += 64) {
        __syncthreads();   // previous PV reads done; also covers Qs stores (iter 0)

        // Stage K (transposed [d][k]) and V ([k][d]) tiles
        #pragma unroll
        for (int it = 0; it < 4; it++) {
            int idx = tid + it * 256;
            int r   = idx >> 4;
            int c   = idx & 15;
            float4 kv = *(const float4*)(Kb + (size_t)(j0 + r) * HD + c * 4);
            Ks[c * 4 + 0][r] = kv.x; Ks[c * 4 + 1][r] = kv.y;
            Ks[c * 4 + 2][r] = kv.z; Ks[c * 4 + 3][r] = kv.w;
            float4 vv = *(const float4*)(Vb + (size_t)(j0 + r) * HD + c * 4);
            Vs[r][c * 4 + 0] = vv.x; Vs[r][c * 4 + 1] = vv.y;
            Vs[r][c * 4 + 2] = vv.z; Vs[r][c * 4 + 3] = vv.w;
        }
        __syncthreads();

        // S = Q K^T  (K-dim = HD = 64)
        float s[4][4];
        #pragma unroll
        for (int i = 0; i < 4; i++)
            #pragma unroll
            for (int j = 0; j < 4; j++) s[i][j] = 0.f;

        #pragma unroll 8
        for (int dd = 0; dd < HD; dd++) {
            float a[4], bb[4];
            #pragma unroll
            for (int i = 0; i < 4; i++) a[i]  = Qs[dd][ty * 4 + i];
            #pragma unroll
            for (int j = 0; j < 4; j++) bb[j] = Ks[dd][tx * 4 + j];
            #pragma unroll
            for (int i = 0; i < 4; i++)
                #pragma unroll
                for (int j = 0; j < 4; j++)
                    s[i][j] = fmaf(a[i], bb[j], s[i][j]);
        }

        // Scale + causal + attention_mask (use -1e30, NaN-free)
        int km[4];
        #pragma unroll
        for (int j = 0; j < 4; j++)
            km[j] = amask[b_ * S_LEN + j0 + tx * 4 + j];
        #pragma unroll
        for (int i = 0; i < 4; i++) {
            int qg = q0 + ty * 4 + i;
            #pragma unroll
            for (int j = 0; j < 4; j++) {
                int kg = j0 + tx * 4 + j;
                float v = s[i][j] * 0.125f;     // 1/sqrt(64)
                if (kg > qg || km[j] == 0) v = -1e30f;
                s[i][j] = v;
            }
        }

        // Online softmax (row reductions across the 16 tx lanes)
        #pragma unroll
        for (int i = 0; i < 4; i++) {
            float mt = fmaxf(fmaxf(s[i][0], s[i][1]), fmaxf(s[i][2], s[i][3]));
            #pragma unroll
            for (int off = 8; off >= 1; off >>= 1)
                mt = fmaxf(mt, __shfl_xor_sync(0xffffffffu, mt, off, 16));
            float mn = fmaxf(m_run[i], mt);
            float alpha = __expf(m_run[i] - mn);
            m_run[i] = mn;

            float lt = 0.f;
            #pragma unroll
            for (int j = 0; j < 4; j++) {
                float p = __expf(s[i][j] - mn);
                s[i][j] = p;
                lt += p;
            }
            #pragma unroll
            for (int off = 8; off >= 1; off >>= 1)
                lt += __shfl_xor_sync(0xffffffffu, lt, off, 16);

            l_run[i] = l_run[i] * alpha + lt;
            #pragma unroll
            for (int j = 0; j < 4; j++) acc[i][j] *= alpha;
        }

        // Stage P transposed [k][q]
        #pragma unroll
        for (int i = 0; i < 4; i++)
            #pragma unroll
            for (int j = 0; j < 4; j++)
                Ps[tx * 4 + j][ty * 4 + i] = s[i][j];
        __syncthreads();

        // acc += P @ V
        #pragma unroll 8
        for (int kk = 0; kk < 64; kk++) {
            float a[4], bb[4];
            #pragma unroll
            for (int i = 0; i < 4; i++) a[i]  = Ps[kk][ty * 4 + i];
            #pragma unroll
            for (int j = 0; j < 4; j++) bb[j] = Vs[kk][tx * 4 + j];
            #pragma unroll
            for (int i = 0; i < 4; i++)
                #pragma unroll
                for (int j = 0; j < 4; j++)
                    acc[i][j] = fmaf(a[i], bb[j], acc[i][j]);
        }
    }

    // Epilogue: normalize, write [b, s, h*HD + d]
    #pragma unroll
    for (int i = 0; i < 4; i++) {
        int qg = q0 + ty * 4 + i;
        float inv_l = 1.0f / l_run[i];
        #pragma unroll
        for (int j = 0; j < 4; j++) {
            out[(size_t)(b_ * S_LEN + qg) * D_MODEL + h * HD + tx * 4 + j] =
                acc[i][j] * inv_l;
        }
    }
}

// ---------------------------------------------------------------------------
extern "C" void kernel_launch(void* const* d_in, const int* in_sizes, int n_in,
                              void* d_out, int out_size)
{
    (void)in_sizes; (void)n_in; (void)out_size;
    const float* hs    = (const float*)d_in[0];
    const int*   amask = (const int*)  d_in[1];
    const float* Wq    = (const float*)d_in[2];
    const float* bq    = (const float*)d_in[3];
    const float* Wk    = (const float*)d_in[4];
    const float* bk    = (const float*)d_in[5];
    const float* Wv    = (const float*)d_in[6];
    const float* bv    = (const float*)d_in[7];
    float* out = (float*)d_out;

    dim3 blk(16, 16);
    dim3 ggrid(D_MODEL / BN, M_TOTAL / BM, 3);   // (16, 128, 3)
    qkv_gemm<<<ggrid, blk>>>(hs, Wq, bq, Wk, bk, Wv, bv);

    const int attn_smem = 4 * 64 * 65 * (int)sizeof(float);  // 66560 B
    cudaFuncSetAttribute(attn_kernel,
                         cudaFuncAttributeMaxDynamicSharedMemorySize, attn_smem);
    attn_kernel<<<dim3(32, 64), blk, attn_smem>>>(amask, out);
}

// round 5
// speedup vs baseline: 1.7067x; 1.7067x over previous
#include <cuda_runtime.h>
#include <math.h>

#define S_LEN   2048
#define D_MODEL 1024
#define NH      16
#define HD      64
#define BATCH   4
#define M_TOTAL (BATCH * S_LEN)          // 8192
#define PLANE   (8192 * 1024)            // elems per Q/K/V plane

// Scratch for Q,K,V in [b,h,s,d] layout (3 * 32MB). __device__ globals are the
// sanctioned scratch mechanism (allocation-free rule).
__device__ float g_qkv[3ull * PLANE];

// ---------------------------------------------------------------------------
// tf32 mma helpers (m16n8k8, row.col, f32 accumulate)
// ---------------------------------------------------------------------------
__device__ __forceinline__ unsigned f2tf(float f) {
    unsigned u;
    asm("cvt.rna.tf32.f32 %0, %1;" : "=r"(u) : "f"(f));
    return u;
}

__device__ __forceinline__ void mma_tf32(float c[4], const unsigned a[4],
                                         const unsigned b[2]) {
    asm volatile(
        "mma.sync.aligned.m16n8k8.row.col.f32.tf32.tf32.f32 "
        "{%0,%1,%2,%3}, {%4,%5,%6,%7}, {%8,%9}, {%0,%1,%2,%3};"
        : "+f"(c[0]), "+f"(c[1]), "+f"(c[2]), "+f"(c[3])
        : "r"(a[0]), "r"(a[1]), "r"(a[2]), "r"(a[3]), "r"(b[0]), "r"(b[1]));
}

// ---------------------------------------------------------------------------
// Kernel 1: fused QKV projection, tf32 tensor cores.  C = X @ W^T + b
//   X: [8192,1024] row-major. W: [1024,1024] row-major (torch Linear weight),
//   which IS the col-major k x n B operand mma.row.col wants (B[k][n]=W[n][k]).
// Block tile 128x128, K-chunk 32, 8 warps (2 m x 4 n), warp tile 64x32.
// Smem tiles [row][k] with +4 pad -> fragment loads are bank-conflict-free
// (addr = row*36 + k; lane>>2 spans 8 rows -> banks 4*row+k hit all 32).
// Output scattered directly to [b,h,s,d] so attention reads contiguously.
// ---------------------------------------------------------------------------
#define GBM 128
#define GBN 128
#define GBK 32

__global__ __launch_bounds__(256) void qkv_gemm_tf32(
    const float* __restrict__ X,
    const float* __restrict__ Wq, const float* __restrict__ bq,
    const float* __restrict__ Wk, const float* __restrict__ bk,
    const float* __restrict__ Wv, const float* __restrict__ bv)
{
    const int z = blockIdx.z;
    const float* W    = (z == 0) ? Wq : (z == 1) ? Wk : Wv;
    const float* bias = (z == 0) ? bq : (z == 1) ? bk : bv;
    float* Out = g_qkv + (size_t)z * PLANE;

    __shared__ unsigned As[GBM][GBK + 4];   // X tile  [m][k], tf32 bits
    __shared__ unsigned Bs[GBN][GBK + 4];   // W tile  [n][k], tf32 bits

    const int tid    = threadIdx.x;
    const int warp   = tid >> 5;
    const int lane   = tid & 31;
    const int grp    = lane >> 2;        // 0..7
    const int lk     = lane & 3;         // 0..3
    const int warp_m = warp >> 2;        // 0..1  -> 64 rows each
    const int warp_n = warp & 3;         // 0..3  -> 32 cols each
    const int m0 = blockIdx.y * GBM;
    const int n0 = blockIdx.x * GBN;

    float acc[4][4][4];                  // [mi][ni][reg]
    #pragma unroll
    for (int mi = 0; mi < 4; mi++)
        #pragma unroll
        for (int ni = 0; ni < 4; ni++)
            #pragma unroll
            for (int r = 0; r < 4; r++) acc[mi][ni][r] = 0.f;

    for (int k0 = 0; k0 < D_MODEL; k0 += GBK) {
        // Stage tiles: 128x32 floats each = 1024 float4, 256 threads -> 4 each
        #pragma unroll
        for (int it = 0; it < 4; it++) {
            int idx = tid + it * 256;            // 0..1023
            int r   = idx >> 3;                  // row 0..127
            int c4  = idx & 7;                   // float4 col 0..7
            float4 a = *(const float4*)(X + (size_t)(m0 + r) * D_MODEL + k0 + c4 * 4);
            uint4 ua = { f2tf(a.x), f2tf(a.y), f2tf(a.z), f2tf(a.w) };
            *(uint4*)&As[r][c4 * 4] = ua;
            float4 b = *(const float4*)(W + (size_t)(n0 + r) * D_MODEL + k0 + c4 * 4);
            uint4 ub = { f2tf(b.x), f2tf(b.y), f2tf(b.z), f2tf(b.w) };
            *(uint4*)&Bs[r][c4 * 4] = ub;
        }
        __syncthreads();

        #pragma unroll
        for (int kk = 0; kk < GBK; kk += 8) {
            unsigned a[4][4];                    // [mi][reg]
            #pragma unroll
            for (int mi = 0; mi < 4; mi++) {
                int rb = warp_m * 64 + mi * 16 + grp;
                a[mi][0] = As[rb    ][kk + lk    ];
                a[mi][1] = As[rb + 8][kk + lk    ];
                a[mi][2] = As[rb    ][kk + lk + 4];
                a[mi][3] = As[rb + 8][kk + lk + 4];
            }
            unsigned b[4][2];                    // [ni][reg]
            #pragma unroll
            for (int ni = 0; ni < 4; ni++) {
                int nb = warp_n * 32 + ni * 8 + grp;
                b[ni][0] = Bs[nb][kk + lk    ];
                b[ni][1] = Bs[nb][kk + lk + 4];
            }
            #pragma unroll
            for (int mi = 0; mi < 4; mi++)
                #pragma unroll
                for (int ni = 0; ni < 4; ni++)
                    mma_tf32(acc[mi][ni], a[mi], b[ni]);
        }
        __syncthreads();
    }

    // Epilogue: bias + scatter into [b, h, s, d]. C-frag layout:
    // c0/c1: row = grp,   cols 2*lk, 2*lk+1 ; c2/c3: row = grp+8, same cols.
    #pragma unroll
    for (int mi = 0; mi < 4; mi++) {
        #pragma unroll
        for (int half = 0; half < 2; half++) {
            int m  = m0 + warp_m * 64 + mi * 16 + grp + half * 8;
            int b_ = m >> 11;
            int s_ = m & 2047;
            #pragma unroll
            for (int ni = 0; ni < 4; ni++) {
                int n = n0 + warp_n * 32 + ni * 8 + 2 * lk;
                int h = n >> 6;
                int d = n & 63;
                float2 v;
                v.x = acc[mi][ni][half * 2 + 0] + bias[n];
                v.y = acc[mi][ni][half * 2 + 1] + bias[n + 1];
                *(float2*)&Out[(((size_t)(b_ * NH + h) * S_LEN + s_) << 6) + d] = v;
            }
        }
    }
}

// ---------------------------------------------------------------------------
// Kernel 2: causal flash attention, fp32 (unchanged from R4-passing version).
// ---------------------------------------------------------------------------
__global__ __launch_bounds__(256) void attn_kernel(
    const int* __restrict__ amask, float* __restrict__ out)
{
    extern __shared__ float smem[];
    float (*Qs)[65] = (float(*)[65])(smem);                 // [d][q]
    float (*Ks)[65] = (float(*)[65])(smem + 64 * 65);       // [d][k]
    float (*Vs)[65] = (float(*)[65])(smem + 2 * 64 * 65);   // [k][d]
    float (*Ps)[65] = (float(*)[65])(smem + 3 * 64 * 65);   // [k][q]

    const int qt = blockIdx.x;
    const int bh = blockIdx.y;
    const int b_ = bh >> 4;
    const int h  = bh & 15;
    const int q0 = qt * 64;

    const float* Qb = g_qkv + (size_t)bh * S_LEN * HD;
    const float* Kb = g_qkv + (size_t)PLANE + (size_t)bh * S_LEN * HD;
    const float* Vb = g_qkv + 2ull * PLANE + (size_t)bh * S_LEN * HD;

    const int tx = threadIdx.x, ty = threadIdx.y;
    const int tid = ty * 16 + tx;

    #pragma unroll
    for (int it = 0; it < 4; it++) {
        int idx = tid + it * 256;
        int r   = idx >> 4;
        int c   = idx & 15;
        float4 a = *(const float4*)(Qb + (size_t)(q0 + r) * HD + c * 4);
        Qs[c * 4 + 0][r] = a.x; Qs[c * 4 + 1][r] = a.y;
        Qs[c * 4 + 2][r] = a.z; Qs[c * 4 + 3][r] = a.w;
    }

    float m_run[4], l_run[4], acc[4][4];
    #pragma unroll
    for (int i = 0; i < 4; i++) {
        m_run[i] = -1e30f; l_run[i] = 0.f;
        #pragma unroll
        for (int j = 0; j < 4; j++) acc[i][j] = 0.f;
    }

    for (int j0 = 0; j0 <= q0; j0 += 64) {
        __syncthreads();

        #pragma unroll
        for (int it = 0; it < 4; it++) {
            int idx = tid + it * 256;
            int r   = idx >> 4;
            int c   = idx & 15;
            float4 kv = *(const float4*)(Kb + (size_t)(j0 + r) * HD + c * 4);
            Ks[c * 4 + 0][r] = kv.x; Ks[c * 4 + 1][r] = kv.y;
            Ks[c * 4 + 2][r] = kv.z; Ks[c * 4 + 3][r] = kv.w;
            float4 vv = *(const float4*)(Vb + (size_t)(j0 + r) * HD + c * 4);
            Vs[r][c * 4 + 0] = vv.x; Vs[r][c * 4 + 1] = vv.y;
            Vs[r][c * 4 + 2] = vv.z; Vs[r][c * 4 + 3] = vv.w;
        }
        __syncthreads();

        float s[4][4];
        #pragma unroll
        for (int i = 0; i < 4; i++)
            #pragma unroll
            for (int j = 0; j < 4; j++) s[i][j] = 0.f;

        #pragma unroll 8
        for (int dd = 0; dd < HD; dd++) {
            float a[4], bb[4];
            #pragma unroll
            for (int i = 0; i < 4; i++) a[i]  = Qs[dd][ty * 4 + i];
            #pragma unroll
            for (int j = 0; j < 4; j++) bb[j] = Ks[dd][tx * 4 + j];
            #pragma unroll
            for (int i = 0; i < 4; i++)
                #pragma unroll
                for (int j = 0; j < 4; j++)
                    s[i][j] = fmaf(a[i], bb[j], s[i][j]);
        }

        int km[4];
        #pragma unroll
        for (int j = 0; j < 4; j++)
            km[j] = amask[b_ * S_LEN + j0 + tx * 4 + j];
        #pragma unroll
        for (int i = 0; i < 4; i++) {
            int qg = q0 + ty * 4 + i;
            #pragma unroll
            for (int j = 0; j < 4; j++) {
                int kg = j0 + tx * 4 + j;
                float v = s[i][j] * 0.125f;
                if (kg > qg || km[j] == 0) v = -1e30f;
                s[i][j] = v;
            }
        }

        #pragma unroll
        for (int i = 0; i < 4; i++) {
            float mt = fmaxf(fmaxf(s[i][0], s[i][1]), fmaxf(s[i][2], s[i][3]));
            #pragma unroll
            for (int off = 8; off >= 1; off >>= 1)
                mt = fmaxf(mt, __shfl_xor_sync(0xffffffffu, mt, off, 16));
            float mn = fmaxf(m_run[i], mt);
            float alpha = __expf(m_run[i] - mn);
            m_run[i] = mn;

            float lt = 0.f;
            #pragma unroll
            for (int j = 0; j < 4; j++) {
                float p = __expf(s[i][j] - mn);
                s[i][j] = p;
                lt += p;
            }
            #pragma unroll
            for (int off = 8; off >= 1; off >>= 1)
                lt += __shfl_xor_sync(0xffffffffu, lt, off, 16);

            l_run[i] = l_run[i] * alpha + lt;
            #pragma unroll
            for (int j = 0; j < 4; j++) acc[i][j] *= alpha;
        }

        #pragma unroll
        for (int i = 0; i < 4; i++)
            #pragma unroll
            for (int j = 0; j < 4; j++)
                Ps[tx * 4 + j][ty * 4 + i] = s[i][j];
        __syncthreads();

        #pragma unroll 8
        for (int kk = 0; kk < 64; kk++) {
            float a[4], bb[4];
            #pragma unroll
            for (int i = 0; i < 4; i++) a[i]  = Ps[kk][ty * 4 + i];
            #pragma unroll
            for (int j = 0; j < 4; j++) bb[j] = Vs[kk][tx * 4 + j];
            #pragma unroll
            for (int i = 0; i < 4; i++)
                #pragma unroll
                for (int j = 0; j < 4; j++)
                    acc[i][j] = fmaf(a[i], bb[j], acc[i][j]);
        }
    }

    #pragma unroll
    for (int i = 0; i < 4; i++) {
        int qg = q0 + ty * 4 + i;
        float inv_l = 1.0f / l_run[i];
        #pragma unroll
        for (int j = 0; j < 4; j++) {
            out[(size_t)(b_ * S_LEN + qg) * D_MODEL + h * HD + tx * 4 + j] =
                acc[i][j] * inv_l;
        }
    }
}

// ---------------------------------------------------------------------------
extern "C" void kernel_launch(void* const* d_in, const int* in_sizes, int n_in,
                              void* d_out, int out_size)
{
    (void)in_sizes; (void)n_in; (void)out_size;
    const float* hs    = (const float*)d_in[0];
    const int*   amask = (const int*)  d_in[1];
    const float* Wq    = (const float*)d_in[2];
    const float* bq    = (const float*)d_in[3];
    const float* Wk    = (const float*)d_in[4];
    const float* bk    = (const float*)d_in[5];
    const float* Wv    = (const float*)d_in[6];
    const float* bv    = (const float*)d_in[7];
    float* out = (float*)d_out;

    dim3 ggrid(D_MODEL / GBN, M_TOTAL / GBM, 3);   // (8, 64, 3)
    qkv_gemm_tf32<<<ggrid, 256>>>(hs, Wq, bq, Wk, bk, Wv, bv);

    const int attn_smem = 4 * 64 * 65 * (int)sizeof(float);  // 66560 B
    cudaFuncSetAttribute(attn_kernel,
                         cudaFuncAttributeMaxDynamicSharedMemorySize, attn_smem);
    attn_kernel<<<dim3(32, 64), dim3(16, 16), attn_smem>>>(amask, out);
}

// round 6
// speedup vs baseline: 3.4708x; 2.0337x over previous
#include <cuda_runtime.h>
#include <math.h>

#define S_LEN   2048
#define D_MODEL 1024
#define NH      16
#define HD      64
#define BATCH   4
#define M_TOTAL (BATCH * S_LEN)          // 8192
#define PLANE   (8192 * 1024)            // elems per Q/K/V plane

// Scratch for Q,K,V in [b,h,s,d] layout. __device__ globals are the
// sanctioned scratch mechanism (allocation-free rule).
__device__ float g_qkv[3ull * PLANE];

// ---------------------------------------------------------------------------
// tf32 mma helpers (m16n8k8, row.col, f32 accumulate)
// Fragment layouts (verified by R4 projection correctness):
//   A: a0=[grp][lk] a1=[grp+8][lk] a2=[grp][lk+4] a3=[grp+8][lk+4]
//   B (as row-major [n][k]): b0=[n_base+grp][lk] b1=[n_base+grp][lk+4]
//   C: c0=[grp][2lk] c1=[grp][2lk+1] c2=[grp+8][2lk] c3=[grp+8][2lk+1]
// ---------------------------------------------------------------------------
__device__ __forceinline__ unsigned f2tf(float f) {
    unsigned u;
    asm("cvt.rna.tf32.f32 %0, %1;" : "=r"(u) : "f"(f));
    return u;
}

__device__ __forceinline__ void mma_tf32(float c[4], const unsigned a[4],
                                         const unsigned b[2]) {
    asm volatile(
        "mma.sync.aligned.m16n8k8.row.col.f32.tf32.tf32.f32 "
        "{%0,%1,%2,%3}, {%4,%5,%6,%7}, {%8,%9}, {%0,%1,%2,%3};"
        : "+f"(c[0]), "+f"(c[1]), "+f"(c[2]), "+f"(c[3])
        : "r"(a[0]), "r"(a[1]), "r"(a[2]), "r"(a[3]), "r"(b[0]), "r"(b[1]));
}

// ---------------------------------------------------------------------------
// Kernel 1: fused QKV projection, tf32 tensor cores (unchanged from R5-pass).
// ---------------------------------------------------------------------------
#define GBM 128
#define GBN 128
#define GBK 32

__global__ __launch_bounds__(256) void qkv_gemm_tf32(
    const float* __restrict__ X,
    const float* __restrict__ Wq, const float* __restrict__ bq,
    const float* __restrict__ Wk, const float* __restrict__ bk,
    const float* __restrict__ Wv, const float* __restrict__ bv)
{
    const int z = blockIdx.z;
    const float* W    = (z == 0) ? Wq : (z == 1) ? Wk : Wv;
    const float* bias = (z == 0) ? bq : (z == 1) ? bk : bv;
    float* Out = g_qkv + (size_t)z * PLANE;

    __shared__ unsigned As[GBM][GBK + 4];
    __shared__ unsigned Bs[GBN][GBK + 4];

    const int tid    = threadIdx.x;
    const int warp   = tid >> 5;
    const int lane   = tid & 31;
    const int grp    = lane >> 2;
    const int lk     = lane & 3;
    const int warp_m = warp >> 2;
    const int warp_n = warp & 3;
    const int m0 = blockIdx.y * GBM;
    const int n0 = blockIdx.x * GBN;

    float acc[4][4][4];
    #pragma unroll
    for (int mi = 0; mi < 4; mi++)
        #pragma unroll
        for (int ni = 0; ni < 4; ni++)
            #pragma unroll
            for (int r = 0; r < 4; r++) acc[mi][ni][r] = 0.f;

    for (int k0 = 0; k0 < D_MODEL; k0 += GBK) {
        #pragma unroll
        for (int it = 0; it < 4; it++) {
            int idx = tid + it * 256;
            int r   = idx >> 3;
            int c4  = idx & 7;
            float4 a = *(const float4*)(X + (size_t)(m0 + r) * D_MODEL + k0 + c4 * 4);
            uint4 ua = { f2tf(a.x), f2tf(a.y), f2tf(a.z), f2tf(a.w) };
            *(uint4*)&As[r][c4 * 4] = ua;
            float4 b = *(const float4*)(W + (size_t)(n0 + r) * D_MODEL + k0 + c4 * 4);
            uint4 ub = { f2tf(b.x), f2tf(b.y), f2tf(b.z), f2tf(b.w) };
            *(uint4*)&Bs[r][c4 * 4] = ub;
        }
        __syncthreads();

        #pragma unroll
        for (int kk = 0; kk < GBK; kk += 8) {
            unsigned a[4][4];
            #pragma unroll
            for (int mi = 0; mi < 4; mi++) {
                int rb = warp_m * 64 + mi * 16 + grp;
                a[mi][0] = As[rb    ][kk + lk    ];
                a[mi][1] = As[rb + 8][kk + lk    ];
                a[mi][2] = As[rb    ][kk + lk + 4];
                a[mi][3] = As[rb + 8][kk + lk + 4];
            }
            unsigned b[4][2];
            #pragma unroll
            for (int ni = 0; ni < 4; ni++) {
                int nb = warp_n * 32 + ni * 8 + grp;
                b[ni][0] = Bs[nb][kk + lk    ];
                b[ni][1] = Bs[nb][kk + lk + 4];
            }
            #pragma unroll
            for (int mi = 0; mi < 4; mi++)
                #pragma unroll
                for (int ni = 0; ni < 4; ni++)
                    mma_tf32(acc[mi][ni], a[mi], b[ni]);
        }
        __syncthreads();
    }

    #pragma unroll
    for (int mi = 0; mi < 4; mi++) {
        #pragma unroll
        for (int half = 0; half < 2; half++) {
            int m  = m0 + warp_m * 64 + mi * 16 + grp + half * 8;
            int b_ = m >> 11;
            int s_ = m & 2047;
            #pragma unroll
            for (int ni = 0; ni < 4; ni++) {
                int n = n0 + warp_n * 32 + ni * 8 + 2 * lk;
                int h = n >> 6;
                int d = n & 63;
                float2 v;
                v.x = acc[mi][ni][half * 2 + 0] + bias[n];
                v.y = acc[mi][ni][half * 2 + 1] + bias[n + 1];
                *(float2*)&Out[(((size_t)(b_ * NH + h) * S_LEN + s_) << 6) + d] = v;
            }
        }
    }
}

// ---------------------------------------------------------------------------
// Kernel 2: causal flash attention on tf32 tensor cores.
// Block = 64 queries of one (b,h), 4 warps, each warp 16 query rows.
// Key tiles of 64. Online softmax held in C-fragment registers.
// P (C-frag) -> A-frag conversion via quad shuffles (no smem round trip).
// Smem: Q[64][68], K[64][68] (as [key][d], B-operand of QK^T),
//       V^T[64][68] (as [d][key], B-operand of PV). All tf32 bits, +4 pad
//       => conflict-free fragment loads.
// ---------------------------------------------------------------------------
#define QT 64
#define KT 64
#define PAD4 (HD + 4)   // 68

__global__ __launch_bounds__(128) void attn_tc(
    const int* __restrict__ amask, float* __restrict__ out)
{
    extern __shared__ unsigned sm[];
    unsigned (*Qs)[PAD4] = (unsigned(*)[PAD4])(sm);
    unsigned (*Ks)[PAD4] = (unsigned(*)[PAD4])(sm +     QT * PAD4);
    unsigned (*Vs)[PAD4] = (unsigned(*)[PAD4])(sm + 2 * QT * PAD4);

    const int qt = blockIdx.x;
    const int bh = blockIdx.y;
    const int b_ = bh >> 4;
    const int h  = bh & 15;
    const int q0 = qt * QT;

    const float* Qb = g_qkv + (size_t)bh * S_LEN * HD;
    const float* Kb = g_qkv + (size_t)PLANE + (size_t)bh * S_LEN * HD;
    const float* Vb = g_qkv + 2ull * PLANE + (size_t)bh * S_LEN * HD;

    const int tid  = threadIdx.x;
    const int warp = tid >> 5;
    const int lane = tid & 31;
    const int grp  = lane >> 2;     // 0..7
    const int lk   = lane & 3;      // 0..3
    const int q0w  = q0 + warp * 16;

    // ---- stage Q (softmax scale folded in), convert to tf32 ----
    #pragma unroll
    for (int it = 0; it < 8; it++) {
        int idx = tid + it * 128;          // 0..1023
        int r   = idx >> 4;                // q row 0..63
        int c   = idx & 15;                // float4 col
        float4 a = *(const float4*)(Qb + (size_t)(q0 + r) * HD + c * 4);
        uint4 u = { f2tf(a.x * 0.125f), f2tf(a.y * 0.125f),
                    f2tf(a.z * 0.125f), f2tf(a.w * 0.125f) };
        *(uint4*)&Qs[r][c * 4] = u;
    }
    __syncthreads();

    // Q fragments, persistent across key tiles: 8 k-steps x 4 regs
    unsigned aq[8][4];
    {
        const int rb = warp * 16;
        #pragma unroll
        for (int kk = 0; kk < 8; kk++) {
            aq[kk][0] = Qs[rb + grp    ][kk * 8 + lk    ];
            aq[kk][1] = Qs[rb + grp + 8][kk * 8 + lk    ];
            aq[kk][2] = Qs[rb + grp    ][kk * 8 + lk + 4];
            aq[kk][3] = Qs[rb + grp + 8][kk * 8 + lk + 4];
        }
    }

    float m_run[2] = { -1e30f, -1e30f };
    float l_run[2] = { 0.f, 0.f };
    float acc[8][4];
    #pragma unroll
    for (int ni = 0; ni < 8; ni++)
        #pragma unroll
        for (int r = 0; r < 4; r++) acc[ni][r] = 0.f;

    const int qsrc = lane & ~3;
    const int s1   = qsrc | (lk >> 1);
    const int s2   = s1 + 2;

    for (int j0 = 0; j0 <= q0; j0 += KT) {
        __syncthreads();    // previous tile's smem reads complete

        // ---- stage K ([key][d]) and V^T ([d][key]) ----
        #pragma unroll
        for (int it = 0; it < 8; it++) {
            int idx = tid + it * 128;      // 0..1023
            int r   = idx >> 4;            // key 0..63
            int c   = idx & 15;            // float4 col
            float4 kv = *(const float4*)(Kb + (size_t)(j0 + r) * HD + c * 4);
            uint4 u = { f2tf(kv.x), f2tf(kv.y), f2tf(kv.z), f2tf(kv.w) };
            *(uint4*)&Ks[r][c * 4] = u;
            float4 vv = *(const float4*)(Vb + (size_t)(j0 + r) * HD + c * 4);
            Vs[c * 4 + 0][r] = f2tf(vv.x);
            Vs[c * 4 + 1][r] = f2tf(vv.y);
            Vs[c * 4 + 2][r] = f2tf(vv.z);
            Vs[c * 4 + 3][r] = f2tf(vv.w);
        }
        __syncthreads();

        // ---- S = Q K^T  (scores, already scaled) ----
        float s[8][4];
        #pragma unroll
        for (int ni = 0; ni < 8; ni++)
            #pragma unroll
            for (int r = 0; r < 4; r++) s[ni][r] = 0.f;

        #pragma unroll
        for (int kk = 0; kk < 8; kk++) {
            #pragma unroll
            for (int ni = 0; ni < 8; ni++) {
                unsigned b[2];
                b[0] = Ks[ni * 8 + grp][kk * 8 + lk    ];
                b[1] = Ks[ni * 8 + grp][kk * 8 + lk + 4];
                mma_tf32(s[ni], aq[kk], b);
            }
        }

        // ---- causal mask (only tiles touching the diagonal) ----
        if (j0 + KT - 1 > q0w) {
            #pragma unroll
            for (int ni = 0; ni < 8; ni++) {
                int c0 = j0 + ni * 8 + 2 * lk;
                int r0 = q0w + grp;
                if (c0     > r0    ) s[ni][0] = -1e30f;
                if (c0 + 1 > r0    ) s[ni][1] = -1e30f;
                if (c0     > r0 + 8) s[ni][2] = -1e30f;
                if (c0 + 1 > r0 + 8) s[ni][3] = -1e30f;
            }
        }
        // ---- attention_mask (keep-mask per key) ----
        #pragma unroll
        for (int ni = 0; ni < 8; ni++) {
            int2 km = *(const int2*)(amask + b_ * S_LEN + j0 + ni * 8 + 2 * lk);
            if (km.x == 0) { s[ni][0] = -1e30f; s[ni][2] = -1e30f; }
            if (km.y == 0) { s[ni][1] = -1e30f; s[ni][3] = -1e30f; }
        }

        // ---- online softmax on fragments ----
        float mt0 = -1e30f, mt1 = -1e30f;
        #pragma unroll
        for (int ni = 0; ni < 8; ni++) {
            mt0 = fmaxf(mt0, fmaxf(s[ni][0], s[ni][1]));
            mt1 = fmaxf(mt1, fmaxf(s[ni][2], s[ni][3]));
        }
        mt0 = fmaxf(mt0, __shfl_xor_sync(0xffffffffu, mt0, 1, 4));
        mt0 = fmaxf(mt0, __shfl_xor_sync(0xffffffffu, mt0, 2, 4));
        mt1 = fmaxf(mt1, __shfl_xor_sync(0xffffffffu, mt1, 1, 4));
        mt1 = fmaxf(mt1, __shfl_xor_sync(0xffffffffu, mt1, 2, 4));

        float mn0 = fmaxf(m_run[0], mt0);
        float mn1 = fmaxf(m_run[1], mt1);
        float al0 = __expf(m_run[0] - mn0);
        float al1 = __expf(m_run[1] - mn1);
        m_run[0] = mn0; m_run[1] = mn1;

        float lt0 = 0.f, lt1 = 0.f;
        #pragma unroll
        for (int ni = 0; ni < 8; ni++) {
            s[ni][0] = __expf(s[ni][0] - mn0); lt0 += s[ni][0];
            s[ni][1] = __expf(s[ni][1] - mn0); lt0 += s[ni][1];
            s[ni][2] = __expf(s[ni][2] - mn1); lt1 += s[ni][2];
            s[ni][3] = __expf(s[ni][3] - mn1); lt1 += s[ni][3];
        }
        lt0 += __shfl_xor_sync(0xffffffffu, lt0, 1, 4);
        lt0 += __shfl_xor_sync(0xffffffffu, lt0, 2, 4);
        lt1 += __shfl_xor_sync(0xffffffffu, lt1, 1, 4);
        lt1 += __shfl_xor_sync(0xffffffffu, lt1, 2, 4);
        l_run[0] = l_run[0] * al0 + lt0;
        l_run[1] = l_run[1] * al1 + lt1;

        #pragma unroll
        for (int ni = 0; ni < 8; ni++) {
            acc[ni][0] *= al0; acc[ni][1] *= al0;
            acc[ni][2] *= al1; acc[ni][3] *= al1;
        }

        // ---- P (C-frag) -> A-frag via quad shuffles, then acc += P V ----
        #pragma unroll
        for (int kk = 0; kk < 8; kk++) {     // key chunk = P column chunk
            unsigned p0 = f2tf(s[kk][0]), p1 = f2tf(s[kk][1]);
            unsigned p2 = f2tf(s[kk][2]), p3 = f2tf(s[kk][3]);
            unsigned ap[4], t0, t1;
            t0 = __shfl_sync(0xffffffffu, p0, s1);
            t1 = __shfl_sync(0xffffffffu, p1, s1);
            ap[0] = (lk & 1) ? t1 : t0;                 // P[grp][kk8+lk]
            t0 = __shfl_sync(0xffffffffu, p2, s1);
            t1 = __shfl_sync(0xffffffffu, p3, s1);
            ap[1] = (lk & 1) ? t1 : t0;                 // P[grp+8][kk8+lk]
            t0 = __shfl_sync(0xffffffffu, p0, s2);
            t1 = __shfl_sync(0xffffffffu, p1, s2);
            ap[2] = (lk & 1) ? t1 : t0;                 // P[grp][kk8+lk+4]
            t0 = __shfl_sync(0xffffffffu, p2, s2);
            t1 = __shfl_sync(0xffffffffu, p3, s2);
            ap[3] = (lk & 1) ? t1 : t0;                 // P[grp+8][kk8+lk+4]

            #pragma unroll
            for (int ni = 0; ni < 8; ni++) {
                unsigned b[2];
                b[0] = Vs[ni * 8 + grp][kk * 8 + lk    ];
                b[1] = Vs[ni * 8 + grp][kk * 8 + lk + 4];
                mma_tf32(acc[ni], ap, b);
            }
        }
    }

    // ---- epilogue: normalize, write [b, s, h*64 + d] ----
    const float il0 = 1.0f / l_run[0];
    const float il1 = 1.0f / l_run[1];
    const int r0 = q0w + grp;
    const int r1 = r0 + 8;
    #pragma unroll
    for (int ni = 0; ni < 8; ni++) {
        int col = h * HD + ni * 8 + 2 * lk;
        float2 v0 = { acc[ni][0] * il0, acc[ni][1] * il0 };
        float2 v1 = { acc[ni][2] * il1, acc[ni][3] * il1 };
        *(float2*)&out[(size_t)(b_ * S_LEN + r0) * D_MODEL + col] = v0;
        *(float2*)&out[(size_t)(b_ * S_LEN + r1) * D_MODEL + col] = v1;
    }
}

// ---------------------------------------------------------------------------
extern "C" void kernel_launch(void* const* d_in, const int* in_sizes, int n_in,
                              void* d_out, int out_size)
{
    (void)in_sizes; (void)n_in; (void)out_size;
    const float* hs    = (const float*)d_in[0];
    const int*   amask = (const int*)  d_in[1];
    const float* Wq    = (const float*)d_in[2];
    const float* bq    = (const float*)d_in[3];
    const float* Wk    = (const float*)d_in[4];
    const float* bk    = (const float*)d_in[5];
    const float* Wv    = (const float*)d_in[6];
    const float* bv    = (const float*)d_in[7];
    float* out = (float*)d_out;

    dim3 ggrid(D_MODEL / GBN, M_TOTAL / GBM, 3);   // (8, 64, 3)
    qkv_gemm_tf32<<<ggrid, 256>>>(hs, Wq, bq, Wk, bk, Wv, bv);

    const int attn_smem = 3 * QT * PAD4 * (int)sizeof(unsigned);  // 52224 B
    cudaFuncSetAttribute(attn_tc,
                         cudaFuncAttributeMaxDynamicSharedMemorySize, attn_smem);
    attn_tc<<<dim3(S_LEN / QT, BATCH * NH), 128, attn_smem>>>(amask, out);
}

// round 7
// speedup vs baseline: 3.8162x; 1.0995x over previous
#include <cuda_runtime.h>
#include <math.h>

#define S_LEN   2048
#define D_MODEL 1024
#define NH      16
#define HD      64
#define BATCH   4
#define M_TOTAL (BATCH * S_LEN)          // 8192
#define PLANE   (8192 * 1024)            // elems per Q/K/V plane

// Scratch for Q,K,V in [b,h,s,d] layout. __device__ globals are the
// sanctioned scratch mechanism (allocation-free rule).
__device__ float g_qkv[3ull * PLANE];

// ---------------------------------------------------------------------------
// tf32 mma helpers (m16n8k8, row.col, f32 accumulate)
//   A: a0=[grp][lk] a1=[grp+8][lk] a2=[grp][lk+4] a3=[grp+8][lk+4]
//   B (row-major [n][k]): b0=[n+grp][lk] b1=[n+grp][lk+4]
//   C: c0=[grp][2lk] c1=[grp][2lk+1] c2=[grp+8][2lk] c3=[grp+8][2lk+1]
// ---------------------------------------------------------------------------
__device__ __forceinline__ unsigned f2tf(float f) {
    unsigned u;
    asm("cvt.rna.tf32.f32 %0, %1;" : "=r"(u) : "f"(f));
    return u;
}

__device__ __forceinline__ void mma_tf32(float c[4], const unsigned a[4],
                                         const unsigned b[2]) {
    asm volatile(
        "mma.sync.aligned.m16n8k8.row.col.f32.tf32.tf32.f32 "
        "{%0,%1,%2,%3}, {%4,%5,%6,%7}, {%8,%9}, {%0,%1,%2,%3};"
        : "+f"(c[0]), "+f"(c[1]), "+f"(c[2]), "+f"(c[3])
        : "r"(a[0]), "r"(a[1]), "r"(a[2]), "r"(a[3]), "r"(b[0]), "r"(b[1]));
}

__device__ __forceinline__ void cp_async16(void* sp, const void* gp) {
    unsigned saddr = (unsigned)__cvta_generic_to_shared(sp);
    asm volatile("cp.async.cg.shared.global [%0], [%1], 16;\n"
                 :: "r"(saddr), "l"(gp));
}
#define CP_COMMIT() asm volatile("cp.async.commit_group;")
#define CP_WAIT(N)  asm volatile("cp.async.wait_group %0;" :: "n"(N))

// ---------------------------------------------------------------------------
// Kernel 1: fused QKV projection, tf32, cp.async double-buffered.
//   C = X @ W^T + b.  Raw fp32 staged in smem; tf32 cvt at fragment load.
// Block tile 128x128, K-chunk 32, 8 warps (2m x 4n), warp tile 64x32.
// ---------------------------------------------------------------------------
#define GBM 128
#define GBN 128
#define GBK 32
#define GPAD (GBK + 4)               // 36 floats -> 144B rows, 16B aligned
#define GTILE (GBM * GPAD)           // 4608 floats per buffer

__global__ __launch_bounds__(256, 2) void qkv_gemm_tf32(
    const float* __restrict__ X,
    const float* __restrict__ Wq, const float* __restrict__ bq,
    const float* __restrict__ Wk, const float* __restrict__ bk,
    const float* __restrict__ Wv, const float* __restrict__ bv)
{
    extern __shared__ float psm[];   // As[2][128][36] | Bs[2][128][36]

    const int z = blockIdx.z;
    const float* W    = (z == 0) ? Wq : (z == 1) ? Wk : Wv;
    const float* bias = (z == 0) ? bq : (z == 1) ? bk : bv;
    float* Out = g_qkv + (size_t)z * PLANE;

    const int tid    = threadIdx.x;
    const int warp   = tid >> 5;
    const int lane   = tid & 31;
    const int grp    = lane >> 2;
    const int lk     = lane & 3;
    const int warp_m = warp >> 2;
    const int warp_n = warp & 3;
    const int m0 = blockIdx.y * GBM;
    const int n0 = blockIdx.x * GBN;

    // staging coords (4 x 16B per thread per operand)
    const int sr  = tid >> 3;        // row 0..31 (x4 iterations -> 128)
    const int sc4 = tid & 7;         // float4 col 0..7

    float acc[4][4][4];
    #pragma unroll
    for (int mi = 0; mi < 4; mi++)
        #pragma unroll
        for (int ni = 0; ni < 4; ni++)
            #pragma unroll
            for (int r = 0; r < 4; r++) acc[mi][ni][r] = 0.f;

    // prologue: stage k0 = 0 into buffer 0
    #pragma unroll
    for (int it = 0; it < 4; it++) {
        int r = sr + it * 32;
        cp_async16(&psm[r * GPAD + sc4 * 4],
                   X + (size_t)(m0 + r) * D_MODEL + sc4 * 4);
        cp_async16(&psm[2 * GTILE + r * GPAD + sc4 * 4],
                   W + (size_t)(n0 + r) * D_MODEL + sc4 * 4);
    }
    CP_COMMIT();

    int p = 0;
    for (int k0 = 0; k0 < D_MODEL; k0 += GBK) {
        if (k0 + GBK < D_MODEL) {
            int q = p ^ 1;
            #pragma unroll
            for (int it = 0; it < 4; it++) {
                int r = sr + it * 32;
                cp_async16(&psm[q * GTILE + r * GPAD + sc4 * 4],
                           X + (size_t)(m0 + r) * D_MODEL + k0 + GBK + sc4 * 4);
                cp_async16(&psm[(2 + q) * GTILE + r * GPAD + sc4 * 4],
                           W + (size_t)(n0 + r) * D_MODEL + k0 + GBK + sc4 * 4);
            }
            CP_COMMIT();
            CP_WAIT(1);
        } else {
            CP_WAIT(0);
        }
        __syncthreads();

        const float* Asb = psm + p * GTILE;
        const float* Bsb = psm + (2 + p) * GTILE;

        #pragma unroll
        for (int kk = 0; kk < GBK; kk += 8) {
            unsigned a[4][4];
            #pragma unroll
            for (int mi = 0; mi < 4; mi++) {
                int rb = warp_m * 64 + mi * 16 + grp;
                a[mi][0] = f2tf(Asb[(rb    ) * GPAD + kk + lk    ]);
                a[mi][1] = f2tf(Asb[(rb + 8) * GPAD + kk + lk    ]);
                a[mi][2] = f2tf(Asb[(rb    ) * GPAD + kk + lk + 4]);
                a[mi][3] = f2tf(Asb[(rb + 8) * GPAD + kk + lk + 4]);
            }
            unsigned b[4][2];
            #pragma unroll
            for (int ni = 0; ni < 4; ni++) {
                int nb = warp_n * 32 + ni * 8 + grp;
                b[ni][0] = f2tf(Bsb[nb * GPAD + kk + lk    ]);
                b[ni][1] = f2tf(Bsb[nb * GPAD + kk + lk + 4]);
            }
            #pragma unroll
            for (int mi = 0; mi < 4; mi++)
                #pragma unroll
                for (int ni = 0; ni < 4; ni++)
                    mma_tf32(acc[mi][ni], a[mi], b[ni]);
        }
        __syncthreads();    // reads of buf p done before it is refilled
        p ^= 1;
    }

    // epilogue: bias + scatter into [b, h, s, d]
    #pragma unroll
    for (int mi = 0; mi < 4; mi++) {
        #pragma unroll
        for (int half = 0; half < 2; half++) {
            int m  = m0 + warp_m * 64 + mi * 16 + grp + half * 8;
            int b_ = m >> 11;
            int s_ = m & 2047;
            #pragma unroll
            for (int ni = 0; ni < 4; ni++) {
                int n = n0 + warp_n * 32 + ni * 8 + 2 * lk;
                int h = n >> 6;
                int d = n & 63;
                float2 v;
                v.x = acc[mi][ni][half * 2 + 0] + bias[n];
                v.y = acc[mi][ni][half * 2 + 1] + bias[n + 1];
                *(float2*)&Out[(((size_t)(b_ * NH + h) * S_LEN + s_) << 6) + d] = v;
            }
        }
    }
}

// ---------------------------------------------------------------------------
// Kernel 2: causal flash attention, tf32 tensor cores.
// Block = 256 queries of one (b,h), 8 warps, each warp 32 query rows (mi=2).
// K/V double-buffered in smem with register prefetch of the next tile.
// V staged transposed [d][key] with a conflict-free thread mapping
// (each warp's 32 lanes write 32 distinct keys of one d-row).
// ---------------------------------------------------------------------------
#define QT   256
#define KT   64
#define PAD4 (HD + 4)   // 68

__global__ __launch_bounds__(256, 1) void attn_tc(
    const int* __restrict__ amask, float* __restrict__ out)
{
    extern __shared__ unsigned sm[];
    unsigned (*Qs)[PAD4]   = (unsigned(*)[PAD4])(sm);                        // [256][68]
    unsigned (*Ksb[2])[PAD4];
    unsigned (*Vsb[2])[PAD4];
    Ksb[0] = (unsigned(*)[PAD4])(sm + (QT      ) * PAD4);
    Ksb[1] = (unsigned(*)[PAD4])(sm + (QT +  64) * PAD4);
    Vsb[0] = (unsigned(*)[PAD4])(sm + (QT + 128) * PAD4);
    Vsb[1] = (unsigned(*)[PAD4])(sm + (QT + 192) * PAD4);

    const int qt = (gridDim.x - 1) - blockIdx.x;   // heavy blocks first
    const int bh = blockIdx.y;
    const int b_ = bh >> 4;
    const int h  = bh & 15;
    const int q0 = qt * QT;

    const float* Qb = g_qkv + (size_t)bh * S_LEN * HD;
    const float* Kb = g_qkv + (size_t)PLANE + (size_t)bh * S_LEN * HD;
    const float* Vb = g_qkv + 2ull * PLANE + (size_t)bh * S_LEN * HD;

    const int tid  = threadIdx.x;
    const int warp = tid >> 5;
    const int lane = tid & 31;
    const int grp  = lane >> 2;
    const int lk   = lane & 3;
    const int q0w  = q0 + warp * 32;

    // ---- stage Q (scale folded), tf32 ----
    #pragma unroll
    for (int it = 0; it < 16; it++) {
        int idx = tid + it * 256;          // 0..4095
        int r   = idx >> 4;                // q row 0..255
        int c   = idx & 15;
        float4 a = *(const float4*)(Qb + (size_t)(q0 + r) * HD + c * 4);
        uint4 u = { f2tf(a.x * 0.125f), f2tf(a.y * 0.125f),
                    f2tf(a.z * 0.125f), f2tf(a.w * 0.125f) };
        *(uint4*)&Qs[r][c * 4] = u;
    }

    // staging coords: K by [key][d] rows; V by key-within-lane (transpose)
    const int kr  = tid >> 4;              // K: key row (x4 it -> 64)
    const int kc  = tid & 15;              // K: float4 col
    const int vkey = tid & 63;             // V: key index
    const int vc   = tid >> 6;             // V: float4 d-chunk 0..3 (x4 it -> 16)

    float4 rk[4], rv[4];
    // prefetch tile j0 = 0
    #pragma unroll
    for (int it = 0; it < 4; it++) {
        rk[it] = *(const float4*)(Kb + (size_t)(kr + it * 16) * HD + kc * 4);
        rv[it] = *(const float4*)(Vb + (size_t)vkey * HD + (vc + it * 4) * 4);
    }
    // store into buffer 0
    #pragma unroll
    for (int it = 0; it < 4; it++) {
        uint4 u = { f2tf(rk[it].x), f2tf(rk[it].y), f2tf(rk[it].z), f2tf(rk[it].w) };
        *(uint4*)&Ksb[0][kr + it * 16][kc * 4] = u;
        int d0 = (vc + it * 4) * 4;
        Vsb[0][d0 + 0][vkey] = f2tf(rv[it].x);
        Vsb[0][d0 + 1][vkey] = f2tf(rv[it].y);
        Vsb[0][d0 + 2][vkey] = f2tf(rv[it].z);
        Vsb[0][d0 + 3][vkey] = f2tf(rv[it].w);
    }

    float m_run[4] = { -1e30f, -1e30f, -1e30f, -1e30f };   // [mi*2+half]
    float l_run[4] = { 0.f, 0.f, 0.f, 0.f };
    float acc[2][8][4];
    #pragma unroll
    for (int mi = 0; mi < 2; mi++)
        #pragma unroll
        for (int ni = 0; ni < 8; ni++)
            #pragma unroll
            for (int r = 0; r < 4; r++) acc[mi][ni][r] = 0.f;

    const int qsrc = lane & ~3;
    const int s1   = qsrc | (lk >> 1);
    const int s2   = s1 + 2;
    const int jmax = q0 + QT - KT;
    int p = 0;

    for (int j0 = 0; j0 <= jmax; j0 += KT) {
        __syncthreads();                   // buffer p filled & prior reads done
        const bool has_next = (j0 + KT) <= jmax;
        if (has_next) {
            #pragma unroll
            for (int it = 0; it < 4; it++) {
                rk[it] = *(const float4*)(Kb + (size_t)(j0 + KT + kr + it * 16) * HD + kc * 4);
                rv[it] = *(const float4*)(Vb + (size_t)(j0 + KT + vkey) * HD + (vc + it * 4) * 4);
            }
        }
        unsigned (*Kp)[PAD4] = Ksb[p];
        unsigned (*Vp)[PAD4] = Vsb[p];

        if (j0 <= q0w + 31) {              // warp-uniform: tile not fully masked
            // ---- S = Q K^T ----
            float s[2][8][4];
            #pragma unroll
            for (int mi = 0; mi < 2; mi++)
                #pragma unroll
                for (int ni = 0; ni < 8; ni++)
                    #pragma unroll
                    for (int r = 0; r < 4; r++) s[mi][ni][r] = 0.f;

            #pragma unroll
            for (int kk = 0; kk < 8; kk++) {
                unsigned a0[4], a1[4];
                const int rb = warp * 32;
                a0[0] = Qs[rb + grp     ][kk * 8 + lk    ];
                a0[1] = Qs[rb + grp +  8][kk * 8 + lk    ];
                a0[2] = Qs[rb + grp     ][kk * 8 + lk + 4];
                a0[3] = Qs[rb + grp +  8][kk * 8 + lk + 4];
                a1[0] = Qs[rb + grp + 16][kk * 8 + lk    ];
                a1[1] = Qs[rb + grp + 24][kk * 8 + lk    ];
                a1[2] = Qs[rb + grp + 16][kk * 8 + lk + 4];
                a1[3] = Qs[rb + grp + 24][kk * 8 + lk + 4];
                #pragma unroll
                for (int ni = 0; ni < 8; ni++) {
                    unsigned b[2];
                    b[0] = Kp[ni * 8 + grp][kk * 8 + lk    ];
                    b[1] = Kp[ni * 8 + grp][kk * 8 + lk + 4];
                    mma_tf32(s[0][ni], a0, b);
                    mma_tf32(s[1][ni], a1, b);
                }
            }

            // ---- causal mask ----
            if (j0 + KT - 1 > q0w) {
                #pragma unroll
                for (int mi = 0; mi < 2; mi++) {
                    int r0 = q0w + mi * 16 + grp;
                    #pragma unroll
                    for (int ni = 0; ni < 8; ni++) {
                        int c0 = j0 + ni * 8 + 2 * lk;
                        if (c0     > r0    ) s[mi][ni][0] = -1e30f;
                        if (c0 + 1 > r0    ) s[mi][ni][1] = -1e30f;
                        if (c0     > r0 + 8) s[mi][ni][2] = -1e30f;
                        if (c0 + 1 > r0 + 8) s[mi][ni][3] = -1e30f;
                    }
                }
            }
            // ---- attention keep-mask ----
            #pragma unroll
            for (int ni = 0; ni < 8; ni++) {
                int2 km = *(const int2*)(amask + b_ * S_LEN + j0 + ni * 8 + 2 * lk);
                if (km.x == 0) {
                    s[0][ni][0] = -1e30f; s[0][ni][2] = -1e30f;
                    s[1][ni][0] = -1e30f; s[1][ni][2] = -1e30f;
                }
                if (km.y == 0) {
                    s[0][ni][1] = -1e30f; s[0][ni][3] = -1e30f;
                    s[1][ni][1] = -1e30f; s[1][ni][3] = -1e30f;
                }
            }

            // ---- online softmax per mi ----
            #pragma unroll
            for (int mi = 0; mi < 2; mi++) {
                float mt0 = -1e30f, mt1 = -1e30f;
                #pragma unroll
                for (int ni = 0; ni < 8; ni++) {
                    mt0 = fmaxf(mt0, fmaxf(s[mi][ni][0], s[mi][ni][1]));
                    mt1 = fmaxf(mt1, fmaxf(s[mi][ni][2], s[mi][ni][3]));
                }
                mt0 = fmaxf(mt0, __shfl_xor_sync(0xffffffffu, mt0, 1, 4));
                mt0 = fmaxf(mt0, __shfl_xor_sync(0xffffffffu, mt0, 2, 4));
                mt1 = fmaxf(mt1, __shfl_xor_sync(0xffffffffu, mt1, 1, 4));
                mt1 = fmaxf(mt1, __shfl_xor_sync(0xffffffffu, mt1, 2, 4));

                float mn0 = fmaxf(m_run[mi * 2 + 0], mt0);
                float mn1 = fmaxf(m_run[mi * 2 + 1], mt1);
                float al0 = __expf(m_run[mi * 2 + 0] - mn0);
                float al1 = __expf(m_run[mi * 2 + 1] - mn1);
                m_run[mi * 2 + 0] = mn0;
                m_run[mi * 2 + 1] = mn1;

                float lt0 = 0.f, lt1 = 0.f;
                #pragma unroll
                for (int ni = 0; ni < 8; ni++) {
                    s[mi][ni][0] = __expf(s[mi][ni][0] - mn0); lt0 += s[mi][ni][0];
                    s[mi][ni][1] = __expf(s[mi][ni][1] - mn0); lt0 += s[mi][ni][1];
                    s[mi][ni][2] = __expf(s[mi][ni][2] - mn1); lt1 += s[mi][ni][2];
                    s[mi][ni][3] = __expf(s[mi][ni][3] - mn1); lt1 += s[mi][ni][3];
                }
                lt0 += __shfl_xor_sync(0xffffffffu, lt0, 1, 4);
                lt0 += __shfl_xor_sync(0xffffffffu, lt0, 2, 4);
                lt1 += __shfl_xor_sync(0xffffffffu, lt1, 1, 4);
                lt1 += __shfl_xor_sync(0xffffffffu, lt1, 2, 4);
                l_run[mi * 2 + 0] = l_run[mi * 2 + 0] * al0 + lt0;
                l_run[mi * 2 + 1] = l_run[mi * 2 + 1] * al1 + lt1;

                #pragma unroll
                for (int ni = 0; ni < 8; ni++) {
                    acc[mi][ni][0] *= al0; acc[mi][ni][1] *= al0;
                    acc[mi][ni][2] *= al1; acc[mi][ni][3] *= al1;
                }
            }

            // ---- P -> A-frags (quad shuffles), acc += P V ----
            #pragma unroll
            for (int kk = 0; kk < 8; kk++) {
                unsigned ap0[4], ap1[4];
                #pragma unroll
                for (int mi = 0; mi < 2; mi++) {
                    unsigned p0 = f2tf(s[mi][kk][0]), p1 = f2tf(s[mi][kk][1]);
                    unsigned p2 = f2tf(s[mi][kk][2]), p3 = f2tf(s[mi][kk][3]);
                    unsigned* ap = mi ? ap1 : ap0;
                    unsigned t0, t1;
                    t0 = __shfl_sync(0xffffffffu, p0, s1);
                    t1 = __shfl_sync(0xffffffffu, p1, s1);
                    ap[0] = (lk & 1) ? t1 : t0;
                    t0 = __shfl_sync(0xffffffffu, p2, s1);
                    t1 = __shfl_sync(0xffffffffu, p3, s1);
                    ap[1] = (lk & 1) ? t1 : t0;
                    t0 = __shfl_sync(0xffffffffu, p0, s2);
                    t1 = __shfl_sync(0xffffffffu, p1, s2);
                    ap[2] = (lk & 1) ? t1 : t0;
                    t0 = __shfl_sync(0xffffffffu, p2, s2);
                    t1 = __shfl_sync(0xffffffffu, p3, s2);
                    ap[3] = (lk & 1) ? t1 : t0;
                }
                #pragma unroll
                for (int ni = 0; ni < 8; ni++) {
                    unsigned b[2];
                    b[0] = Vp[ni * 8 + grp][kk * 8 + lk    ];
                    b[1] = Vp[ni * 8 + grp][kk * 8 + lk + 4];
                    mma_tf32(acc[0][ni], ap0, b);
                    mma_tf32(acc[1][ni], ap1, b);
                }
            }
        }

        if (has_next) {
            int q = p ^ 1;
            #pragma unroll
            for (int it = 0; it < 4; it++) {
                uint4 u = { f2tf(rk[it].x), f2tf(rk[it].y),
                            f2tf(rk[it].z), f2tf(rk[it].w) };
                *(uint4*)&Ksb[q][kr + it * 16][kc * 4] = u;
                int d0 = (vc + it * 4) * 4;
                Vsb[q][d0 + 0][vkey] = f2tf(rv[it].x);
                Vsb[q][d0 + 1][vkey] = f2tf(rv[it].y);
                Vsb[q][d0 + 2][vkey] = f2tf(rv[it].z);
                Vsb[q][d0 + 3][vkey] = f2tf(rv[it].w);
            }
        }
        p ^= 1;
    }

    // ---- epilogue: normalize, write [b, s, h*64 + d] ----
    #pragma unroll
    for (int mi = 0; mi < 2; mi++) {
        const float il0 = 1.0f / l_run[mi * 2 + 0];
        const float il1 = 1.0f / l_run[mi * 2 + 1];
        const int r0 = q0w + mi * 16 + grp;
        const int r1 = r0 + 8;
        #pragma unroll
        for (int ni = 0; ni < 8; ni++) {
            int col = h * HD + ni * 8 + 2 * lk;
            float2 v0 = { acc[mi][ni][0] * il0, acc[mi][ni][1] * il0 };
            float2 v1 = { acc[mi][ni][2] * il1, acc[mi][ni][3] * il1 };
            *(float2*)&out[(size_t)(b_ * S_LEN + r0) * D_MODEL + col] = v0;
            *(float2*)&out[(size_t)(b_ * S_LEN + r1) * D_MODEL + col] = v1;
        }
    }
}

// ---------------------------------------------------------------------------
extern "C" void kernel_launch(void* const* d_in, const int* in_sizes, int n_in,
                              void* d_out, int out_size)
{
    (void)in_sizes; (void)n_in; (void)out_size;
    const float* hs    = (const float*)d_in[0];
    const int*   amask = (const int*)  d_in[1];
    const float* Wq    = (const float*)d_in[2];
    const float* bq    = (const float*)d_in[3];
    const float* Wk    = (const float*)d_in[4];
    const float* bk    = (const float*)d_in[5];
    const float* Wv    = (const float*)d_in[6];
    const float* bv    = (const float*)d_in[7];
    float* out = (float*)d_out;

    const int proj_smem = 4 * GTILE * (int)sizeof(float);   // 73728 B
    cudaFuncSetAttribute(qkv_gemm_tf32,
                         cudaFuncAttributeMaxDynamicSharedMemorySize, proj_smem);
    dim3 ggrid(D_MODEL / GBN, M_TOTAL / GBM, 3);             // (8, 64, 3)
    qkv_gemm_tf32<<<ggrid, 256, proj_smem>>>(hs, Wq, bq, Wk, bk, Wv, bv);

    const int attn_smem = (QT + 4 * 64) * PAD4 * (int)sizeof(unsigned); // 139264 B
    cudaFuncSetAttribute(attn_tc,
                         cudaFuncAttributeMaxDynamicSharedMemorySize, attn_smem);
    attn_tc<<<dim3(S_LEN / QT, BATCH * NH), 256, attn_smem>>>(amask, out);
}

// round 8
// speedup vs baseline: 4.3514x; 1.1402x over previous
#include <cuda_runtime.h>
#include <math.h>

#define S_LEN   2048
#define D_MODEL 1024
#define NH      16
#define HD      64
#define BATCH   4
#define M_TOTAL (BATCH * S_LEN)          // 8192
#define PLANE   (8192 * 1024)            // elems per Q/K/V plane

// Scratch for Q,K,V in [b,h,s,d] layout, values pre-rounded to tf32 (Q also
// pre-scaled by 1/sqrt(HD)). __device__ globals = sanctioned scratch.
__device__ float g_qkv[3ull * PLANE];

// ---------------------------------------------------------------------------
// tf32 mma helpers (m16n8k8, row.col, f32 accumulate)
//   A: a0=[grp][lk] a1=[grp+8][lk] a2=[grp][lk+4] a3=[grp+8][lk+4]
//   B (row-major [n][k]): b0=[n+grp][lk] b1=[n+grp][lk+4]
//   C: c0=[grp][2lk] c1=[grp][2lk+1] c2=[grp+8][2lk] c3=[grp+8][2lk+1]
// ---------------------------------------------------------------------------
__device__ __forceinline__ unsigned f2tf(float f) {
    unsigned u;
    asm("cvt.rna.tf32.f32 %0, %1;" : "=r"(u) : "f"(f));
    return u;
}

__device__ __forceinline__ void mma_tf32(float c[4], const unsigned a[4],
                                         const unsigned b[2]) {
    asm volatile(
        "mma.sync.aligned.m16n8k8.row.col.f32.tf32.tf32.f32 "
        "{%0,%1,%2,%3}, {%4,%5,%6,%7}, {%8,%9}, {%0,%1,%2,%3};"
        : "+f"(c[0]), "+f"(c[1]), "+f"(c[2]), "+f"(c[3])
        : "r"(a[0]), "r"(a[1]), "r"(a[2]), "r"(a[3]), "r"(b[0]), "r"(b[1]));
}

__device__ __forceinline__ void cp_async16(void* sp, const void* gp) {
    unsigned saddr = (unsigned)__cvta_generic_to_shared(sp);
    asm volatile("cp.async.cg.shared.global [%0], [%1], 16;\n"
                 :: "r"(saddr), "l"(gp));
}
#define CP_COMMIT() asm volatile("cp.async.commit_group;")
#define CP_WAIT(N)  asm volatile("cp.async.wait_group %0;" :: "n"(N))

// ---------------------------------------------------------------------------
// Kernel 1: fused QKV projection, tf32, cp.async double-buffered.
//   C = X @ W^T + b.  Epilogue pre-rounds the result to tf32 (rna) and
//   pre-scales Q by 0.125 so the attention kernel needs no cvt at all.
// ---------------------------------------------------------------------------
#define GBM 128
#define GBN 128
#define GBK 32
#define GPAD (GBK + 4)               // 36 floats
#define GTILE (GBM * GPAD)

__global__ __launch_bounds__(256, 2) void qkv_gemm_tf32(
    const float* __restrict__ X,
    const float* __restrict__ Wq, const float* __restrict__ bq,
    const float* __restrict__ Wk, const float* __restrict__ bk,
    const float* __restrict__ Wv, const float* __restrict__ bv)
{
    extern __shared__ float psm[];   // As[2][128][36] | Bs[2][128][36]

    const int z = blockIdx.z;
    const float* W    = (z == 0) ? Wq : (z == 1) ? Wk : Wv;
    const float* bias = (z == 0) ? bq : (z == 1) ? bk : bv;
    const float scale = (z == 0) ? 0.125f : 1.0f;
    float* Out = g_qkv + (size_t)z * PLANE;

    const int tid    = threadIdx.x;
    const int warp   = tid >> 5;
    const int lane   = tid & 31;
    const int grp    = lane >> 2;
    const int lk     = lane & 3;
    const int warp_m = warp >> 2;
    const int warp_n = warp & 3;
    const int m0 = blockIdx.y * GBM;
    const int n0 = blockIdx.x * GBN;

    const int sr  = tid >> 3;
    const int sc4 = tid & 7;

    float acc[4][4][4];
    #pragma unroll
    for (int mi = 0; mi < 4; mi++)
        #pragma unroll
        for (int ni = 0; ni < 4; ni++)
            #pragma unroll
            for (int r = 0; r < 4; r++) acc[mi][ni][r] = 0.f;

    #pragma unroll
    for (int it = 0; it < 4; it++) {
        int r = sr + it * 32;
        cp_async16(&psm[r * GPAD + sc4 * 4],
                   X + (size_t)(m0 + r) * D_MODEL + sc4 * 4);
        cp_async16(&psm[2 * GTILE + r * GPAD + sc4 * 4],
                   W + (size_t)(n0 + r) * D_MODEL + sc4 * 4);
    }
    CP_COMMIT();

    int p = 0;
    for (int k0 = 0; k0 < D_MODEL; k0 += GBK) {
        if (k0 + GBK < D_MODEL) {
            int q = p ^ 1;
            #pragma unroll
            for (int it = 0; it < 4; it++) {
                int r = sr + it * 32;
                cp_async16(&psm[q * GTILE + r * GPAD + sc4 * 4],
                           X + (size_t)(m0 + r) * D_MODEL + k0 + GBK + sc4 * 4);
                cp_async16(&psm[(2 + q) * GTILE + r * GPAD + sc4 * 4],
                           W + (size_t)(n0 + r) * D_MODEL + k0 + GBK + sc4 * 4);
            }
            CP_COMMIT();
            CP_WAIT(1);
        } else {
            CP_WAIT(0);
        }
        __syncthreads();

        const float* Asb = psm + p * GTILE;
        const float* Bsb = psm + (2 + p) * GTILE;

        #pragma unroll
        for (int kk = 0; kk < GBK; kk += 8) {
            unsigned a[4][4];
            #pragma unroll
            for (int mi = 0; mi < 4; mi++) {
                int rb = warp_m * 64 + mi * 16 + grp;
                a[mi][0] = f2tf(Asb[(rb    ) * GPAD + kk + lk    ]);
                a[mi][1] = f2tf(Asb[(rb + 8) * GPAD + kk + lk    ]);
                a[mi][2] = f2tf(Asb[(rb    ) * GPAD + kk + lk + 4]);
                a[mi][3] = f2tf(Asb[(rb + 8) * GPAD + kk + lk + 4]);
            }
            unsigned b[4][2];
            #pragma unroll
            for (int ni = 0; ni < 4; ni++) {
                int nb = warp_n * 32 + ni * 8 + grp;
                b[ni][0] = f2tf(Bsb[nb * GPAD + kk + lk    ]);
                b[ni][1] = f2tf(Bsb[nb * GPAD + kk + lk + 4]);
            }
            #pragma unroll
            for (int mi = 0; mi < 4; mi++)
                #pragma unroll
                for (int ni = 0; ni < 4; ni++)
                    mma_tf32(acc[mi][ni], a[mi], b[ni]);
        }
        __syncthreads();
        p ^= 1;
    }

    // epilogue: bias, pre-scale, round to tf32, scatter into [b, h, s, d]
    #pragma unroll
    for (int mi = 0; mi < 4; mi++) {
        #pragma unroll
        for (int half = 0; half < 2; half++) {
            int m  = m0 + warp_m * 64 + mi * 16 + grp + half * 8;
            int b_ = m >> 11;
            int s_ = m & 2047;
            #pragma unroll
            for (int ni = 0; ni < 4; ni++) {
                int n = n0 + warp_n * 32 + ni * 8 + 2 * lk;
                int h = n >> 6;
                int d = n & 63;
                float2 v;
                v.x = __uint_as_float(f2tf((acc[mi][ni][half * 2 + 0] + bias[n    ]) * scale));
                v.y = __uint_as_float(f2tf((acc[mi][ni][half * 2 + 1] + bias[n + 1]) * scale));
                *(float2*)&Out[(((size_t)(b_ * NH + h) * S_LEN + s_) << 6) + d] = v;
            }
        }
    }
}

// ---------------------------------------------------------------------------
// Kernel 2: causal flash attention, tf32 tensor cores, occupancy-first.
// 128 threads (4 warps), QT=64, each warp 16 query rows. 4 CTAs/SM.
// K/V staged raw by cp.async (values already tf32-rounded by kernel 1).
// K: [key][68] (bank-perfect: grp*4+lk). V: [key][72] row-major — stride
// 72 mod 32 = 8 makes Vs[kk*8+lk][ni*8+grp] hit all 32 banks (lk*8+grp).
// ---------------------------------------------------------------------------
#define QT   64
#define KT   64
#define KPAD 68
#define VPAD 72

__global__ __launch_bounds__(128, 4) void attn_tc(
    const int* __restrict__ amask, float* __restrict__ out)
{
    extern __shared__ unsigned sm[];
    unsigned (*Qs)[KPAD] = (unsigned(*)[KPAD])(sm);                   // [64][68] tf32 bits
    float    (*Ks)[KPAD] = (float(*)[KPAD])(sm +     QT * KPAD);      // [64][68]
    float    (*Vs)[VPAD] = (float(*)[VPAD])(sm + 2 * QT * KPAD);      // [64][72]

    const int qt = (gridDim.x - 1) - blockIdx.x;    // heavy blocks first
    const int bh = blockIdx.y;
    const int b_ = bh >> 4;
    const int h  = bh & 15;
    const int q0 = qt * QT;

    const float* Qb = g_qkv + (size_t)bh * S_LEN * HD;
    const float* Kb = g_qkv + (size_t)PLANE + (size_t)bh * S_LEN * HD;
    const float* Vb = g_qkv + 2ull * PLANE + (size_t)bh * S_LEN * HD;

    const int tid  = threadIdx.x;
    const int warp = tid >> 5;
    const int lane = tid & 31;
    const int grp  = lane >> 2;
    const int lk   = lane & 3;
    const int q0w  = q0 + warp * 16;

    // ---- stage Q bits (already tf32 + scaled): pure copy ----
    #pragma unroll
    for (int it = 0; it < 8; it++) {
        int idx = tid + it * 128;          // 0..1023
        int r   = idx >> 4;                // q row 0..63
        int c   = idx & 15;                // 16B chunk
        uint4 u = *(const uint4*)(Qb + (size_t)(q0 + r) * HD + c * 4);
        *(uint4*)&Qs[r][c * 4] = u;
    }

    float m_run[2] = { -1e30f, -1e30f };
    float l_run[2] = { 0.f, 0.f };
    float acc[8][4];
    #pragma unroll
    for (int ni = 0; ni < 8; ni++)
        #pragma unroll
        for (int r = 0; r < 4; r++) acc[ni][r] = 0.f;

    const int qsrc = lane & ~3;
    const int s1   = qsrc | (lk >> 1);
    const int s2   = s1 + 2;
    const int rb   = warp * 16;

    for (int j0 = 0; j0 <= q0; j0 += KT) {
        __syncthreads();                   // retire previous tile reads (+ Q STS on iter 0)

        // ---- stage K and V raw via cp.async ----
        #pragma unroll
        for (int it = 0; it < 8; it++) {
            int idx = tid + it * 128;      // 0..1023
            int r   = idx >> 4;            // key 0..63
            int c   = idx & 15;
            cp_async16(&Ks[r][c * 4], Kb + (size_t)(j0 + r) * HD + c * 4);
        }
        #pragma unroll
        for (int it = 0; it < 8; it++) {
            int idx = tid + it * 128;
            int r   = idx >> 4;
            int c   = idx & 15;
            cp_async16(&Vs[r][c * 4], Vb + (size_t)(j0 + r) * HD + c * 4);
        }
        CP_COMMIT();
        CP_WAIT(0);
        __syncthreads();

        // ---- S = Q K^T ----
        float s[8][4];
        #pragma unroll
        for (int ni = 0; ni < 8; ni++)
            #pragma unroll
            for (int r = 0; r < 4; r++) s[ni][r] = 0.f;

        #pragma unroll
        for (int kk = 0; kk < 8; kk++) {
            unsigned a[4];
            a[0] = Qs[rb + grp    ][kk * 8 + lk    ];
            a[1] = Qs[rb + grp + 8][kk * 8 + lk    ];
            a[2] = Qs[rb + grp    ][kk * 8 + lk + 4];
            a[3] = Qs[rb + grp + 8][kk * 8 + lk + 4];
            #pragma unroll
            for (int ni = 0; ni < 8; ni++) {
                unsigned b[2];
                b[0] = __float_as_uint(Ks[ni * 8 + grp][kk * 8 + lk    ]);
                b[1] = __float_as_uint(Ks[ni * 8 + grp][kk * 8 + lk + 4]);
                mma_tf32(s[ni], a, b);
            }
        }

        // ---- causal mask (tiles touching the diagonal) ----
        if (j0 + KT - 1 > q0w) {
            int r0 = q0w + grp;
            #pragma unroll
            for (int ni = 0; ni < 8; ni++) {
                int c0 = j0 + ni * 8 + 2 * lk;
                if (c0     > r0    ) s[ni][0] = -1e30f;
                if (c0 + 1 > r0    ) s[ni][1] = -1e30f;
                if (c0     > r0 + 8) s[ni][2] = -1e30f;
                if (c0 + 1 > r0 + 8) s[ni][3] = -1e30f;
            }
        }
        // ---- attention keep-mask ----
        #pragma unroll
        for (int ni = 0; ni < 8; ni++) {
            int2 km = *(const int2*)(amask + b_ * S_LEN + j0 + ni * 8 + 2 * lk);
            if (km.x == 0) { s[ni][0] = -1e30f; s[ni][2] = -1e30f; }
            if (km.y == 0) { s[ni][1] = -1e30f; s[ni][3] = -1e30f; }
        }

        // ---- online softmax ----
        float mt0 = -1e30f, mt1 = -1e30f;
        #pragma unroll
        for (int ni = 0; ni < 8; ni++) {
            mt0 = fmaxf(mt0, fmaxf(s[ni][0], s[ni][1]));
            mt1 = fmaxf(mt1, fmaxf(s[ni][2], s[ni][3]));
        }
        mt0 = fmaxf(mt0, __shfl_xor_sync(0xffffffffu, mt0, 1, 4));
        mt0 = fmaxf(mt0, __shfl_xor_sync(0xffffffffu, mt0, 2, 4));
        mt1 = fmaxf(mt1, __shfl_xor_sync(0xffffffffu, mt1, 1, 4));
        mt1 = fmaxf(mt1, __shfl_xor_sync(0xffffffffu, mt1, 2, 4));

        float mn0 = fmaxf(m_run[0], mt0);
        float mn1 = fmaxf(m_run[1], mt1);
        float al0 = __expf(m_run[0] - mn0);
        float al1 = __expf(m_run[1] - mn1);
        m_run[0] = mn0; m_run[1] = mn1;

        float lt0 = 0.f, lt1 = 0.f;
        #pragma unroll
        for (int ni = 0; ni < 8; ni++) {
            s[ni][0] = __expf(s[ni][0] - mn0); lt0 += s[ni][0];
            s[ni][1] = __expf(s[ni][1] - mn0); lt0 += s[ni][1];
            s[ni][2] = __expf(s[ni][2] - mn1); lt1 += s[ni][2];
            s[ni][3] = __expf(s[ni][3] - mn1); lt1 += s[ni][3];
        }
        lt0 += __shfl_xor_sync(0xffffffffu, lt0, 1, 4);
        lt0 += __shfl_xor_sync(0xffffffffu, lt0, 2, 4);
        lt1 += __shfl_xor_sync(0xffffffffu, lt1, 1, 4);
        lt1 += __shfl_xor_sync(0xffffffffu, lt1, 2, 4);
        l_run[0] = l_run[0] * al0 + lt0;
        l_run[1] = l_run[1] * al1 + lt1;

        #pragma unroll
        for (int ni = 0; ni < 8; ni++) {
            acc[ni][0] *= al0; acc[ni][1] *= al0;
            acc[ni][2] *= al1; acc[ni][3] *= al1;
        }

        // ---- P (C-frag) -> A-frag via quad shuffles, acc += P V ----
        #pragma unroll
        for (int kk = 0; kk < 8; kk++) {
            unsigned p0 = f2tf(s[kk][0]), p1 = f2tf(s[kk][1]);
            unsigned p2 = f2tf(s[kk][2]), p3 = f2tf(s[kk][3]);
            unsigned ap[4], t0, t1;
            t0 = __shfl_sync(0xffffffffu, p0, s1);
            t1 = __shfl_sync(0xffffffffu, p1, s1);
            ap[0] = (lk & 1) ? t1 : t0;
            t0 = __shfl_sync(0xffffffffu, p2, s1);
            t1 = __shfl_sync(0xffffffffu, p3, s1);
            ap[1] = (lk & 1) ? t1 : t0;
            t0 = __shfl_sync(0xffffffffu, p0, s2);
            t1 = __shfl_sync(0xffffffffu, p1, s2);
            ap[2] = (lk & 1) ? t1 : t0;
            t0 = __shfl_sync(0xffffffffu, p2, s2);
            t1 = __shfl_sync(0xffffffffu, p3, s2);
            ap[3] = (lk & 1) ? t1 : t0;

            #pragma unroll
            for (int ni = 0; ni < 8; ni++) {
                unsigned b[2];
                b[0] = __float_as_uint(Vs[kk * 8 + lk    ][ni * 8 + grp]);
                b[1] = __float_as_uint(Vs[kk * 8 + lk + 4][ni * 8 + grp]);
                mma_tf32(acc[ni], ap, b);
            }
        }
    }

    // ---- epilogue: normalize, write [b, s, h*64 + d] ----
    const float il0 = 1.0f / l_run[0];
    const float il1 = 1.0f / l_run[1];
    const int r0 = q0w + grp;
    const int r1 = r0 + 8;
    #pragma unroll
    for (int ni = 0; ni < 8; ni++) {
        int col = h * HD + ni * 8 + 2 * lk;
        float2 v0 = { acc[ni][0] * il0, acc[ni][1] * il0 };
        float2 v1 = { acc[ni][2] * il1, acc[ni][3] * il1 };
        *(float2*)&out[(size_t)(b_ * S_LEN + r0) * D_MODEL + col] = v0;
        *(float2*)&out[(size_t)(b_ * S_LEN + r1) * D_MODEL + col] = v1;
    }
}

// ---------------------------------------------------------------------------
extern "C" void kernel_launch(void* const* d_in, const int* in_sizes, int n_in,
                              void* d_out, int out_size)
{
    (void)in_sizes; (void)n_in; (void)out_size;
    const float* hs    = (const float*)d_in[0];
    const int*   amask = (const int*)  d_in[1];
    const float* Wq    = (const float*)d_in[2];
    const float* bq    = (const float*)d_in[3];
    const float* Wk    = (const float*)d_in[4];
    const float* bk    = (const float*)d_in[5];
    const float* Wv    = (const float*)d_in[6];
    const float* bv    = (const float*)d_in[7];
    float* out = (float*)d_out;

    const int proj_smem = 4 * GTILE * (int)sizeof(float);   // 73728 B
    cudaFuncSetAttribute(qkv_gemm_tf32,
                         cudaFuncAttributeMaxDynamicSharedMemorySize, proj_smem);
    dim3 ggrid(D_MODEL / GBN, M_TOTAL / GBM, 3);             // (8, 64, 3)
    qkv_gemm_tf32<<<ggrid, 256, proj_smem>>>(hs, Wq, bq, Wk, bk, Wv, bv);

    // Qs 64*68 + Ks 64*68 + Vs 64*72, all 4B  => 53248 B per CTA (4 CTAs/SM)
    const int attn_smem = (QT * KPAD + KT * KPAD + KT * VPAD) * (int)sizeof(unsigned);
    cudaFuncSetAttribute(attn_tc,
                         cudaFuncAttributeMaxDynamicSharedMemorySize, attn_smem);
    attn_tc<<<dim3(S_LEN / QT, BATCH * NH), 128, attn_smem>>>(amask, out);
}